// round 7
// baseline (speedup 1.0000x reference)
#include <cuda_runtime.h>
#include <cuda_bf16.h>
#include <math.h>
#include <stdint.h>

#define N_NODES 100000
#define DIM     128
#define N_REL   8
#define N_EDGES 640000

// ---------------- scratch (static device globals; no allocation) -------------
__device__ int   g_cnt   [N_NODES];          // in-degree (int)
__device__ int   g_rowptr[N_NODES + 1];      // CSR by destination col
__device__ int   g_cursor[N_NODES];
__device__ float g_dinv  [N_NODES];
__device__ int2  g_erec  [N_EDGES];          // {row*8+type, coef bits} col-sorted
__device__ float g_xW    [(size_t)N_NODES * N_REL * DIM];   // [N, R, D]
__device__ float g_z1    [(size_t)N_NODES * DIM];
// prepacked, transposed (W^T: [r][j=out][k=in]) bf16 hi/lo weight images
__device__ uint4 g_B1h[16384];   // 8 rel * 32768 B each
__device__ uint4 g_B1l[16384];
__device__ uint4 g_B2h[16384];
__device__ uint4 g_B2l[16384];

// ===================== helpers ===============================================
__device__ __forceinline__ uint32_t smem_u32(const void* p) {
    uint32_t a;
    asm("{ .reg .u64 t; cvta.to.shared.u64 t, %1; cvt.u32.u64 %0, t; }" : "=r"(a) : "l"(p));
    return a;
}

__device__ __forceinline__ void split4(float4 v, uint2& hi, uint2& lo) {
    __nv_bfloat16 h0 = __float2bfloat16(v.x), h1 = __float2bfloat16(v.y);
    __nv_bfloat16 h2 = __float2bfloat16(v.z), h3 = __float2bfloat16(v.w);
    __nv_bfloat16 l0 = __float2bfloat16(v.x - __bfloat162float(h0));
    __nv_bfloat16 l1 = __float2bfloat16(v.y - __bfloat162float(h1));
    __nv_bfloat16 l2 = __float2bfloat16(v.z - __bfloat162float(h2));
    __nv_bfloat16 l3 = __float2bfloat16(v.w - __bfloat162float(h3));
    hi.x = (uint32_t)__bfloat16_as_ushort(h0) | ((uint32_t)__bfloat16_as_ushort(h1) << 16);
    hi.y = (uint32_t)__bfloat16_as_ushort(h2) | ((uint32_t)__bfloat16_as_ushort(h3) << 16);
    lo.x = (uint32_t)__bfloat16_as_ushort(l0) | ((uint32_t)__bfloat16_as_ushort(l1) << 16);
    lo.y = (uint32_t)__bfloat16_as_ushort(l2) | ((uint32_t)__bfloat16_as_ushort(l3) << 16);
}

#define LDSM_X4(r0, r1, r2, r3, addr) \
    asm volatile("ldmatrix.sync.aligned.m8n8.x4.shared.b16 {%0,%1,%2,%3}, [%4];" \
                 : "=r"(r0), "=r"(r1), "=r"(r2), "=r"(r3) : "r"(addr))

#define MMA16816(c, a0, a1, a2, a3, b0, b1) \
    asm volatile("mma.sync.aligned.m16n8k16.row.col.f32.bf16.bf16.f32 " \
                 "{%0,%1,%2,%3}, {%4,%5,%6,%7}, {%8,%9}, {%0,%1,%2,%3};" \
                 : "+f"((c)[0]), "+f"((c)[1]), "+f"((c)[2]), "+f"((c)[3]) \
                 : "r"(a0), "r"(a1), "r"(a2), "r"(a3), "r"(b0), "r"(b1))

#define CP_ASYNC16(dst, src) \
    asm volatile("cp.async.ca.shared.global [%0], [%1], 16;" :: "r"(dst), "l"(src) : "memory")
#define CP_COMMIT() asm volatile("cp.async.commit_group;" ::: "memory")

// ---------------- CSR build ---------------------------------------------------
__global__ void zero_cnt_kernel() {
    int i = blockIdx.x * 256 + threadIdx.x;
    if (i < N_NODES) g_cnt[i] = 0;
}

__global__ void hist_kernel(const int* __restrict__ col) {
    int e = blockIdx.x * 256 + threadIdx.x;
    if (e < N_EDGES) atomicAdd(&g_cnt[col[e]], 1);
}

// single block: exclusive scan of cnt -> rowptr, cursor; dinv from cnt
__global__ __launch_bounds__(1024)
void scan_kernel() {
    __shared__ int part[1024];
    const int CH = (N_NODES + 1023) / 1024;     // 98
    const int t = threadIdx.x;
    const int base = t * CH;
    int s = 0;
    for (int i = 0; i < CH; i++) {
        int idx = base + i;
        if (idx < N_NODES) s += g_cnt[idx];
    }
    part[t] = s;
    __syncthreads();
    for (int off = 1; off < 1024; off <<= 1) {
        int v = 0;
        if (t >= off) v = part[t - off];
        __syncthreads();
        if (t >= off) part[t] += v;
        __syncthreads();
    }
    int run = (t == 0) ? 0 : part[t - 1];
    for (int i = 0; i < CH; i++) {
        int idx = base + i;
        if (idx < N_NODES) {
            g_rowptr[idx] = run;
            g_cursor[idx] = run;
            int c = g_cnt[idx];
            g_dinv[idx] = (c > 0) ? rsqrtf((float)c) : 0.0f;
            run += c;
        }
    }
    if (t == 1023) g_rowptr[N_NODES] = part[1023];
}

__global__ void fill_kernel(const int* __restrict__ row,
                            const int* __restrict__ col,
                            const int* __restrict__ etype,
                            const float* __restrict__ ew) {
    int e = blockIdx.x * 256 + threadIdx.x;
    if (e >= N_EDGES) return;
    int r = row[e], c = col[e], t = etype[e];
    float cf = g_dinv[r] * g_dinv[c] * ew[e];
    int p = atomicAdd(&g_cursor[c], 1);
    g_erec[p] = make_int2(r * N_REL + t, __float_as_int(cf));
}

// ---------------- weight prepack: transpose + bf16-split (both W) ------------
__global__ void prepack_kernel(const float* __restrict__ W1,
                               const float* __restrict__ W2,
                               unsigned char* __restrict__ o1h,
                               unsigned char* __restrict__ o1l,
                               unsigned char* __restrict__ o2h,
                               unsigned char* __restrict__ o2l) {
    int t = blockIdx.x * 256 + threadIdx.x;     // 65536 threads
    if (t >= 2 * N_REL * 128 * 32) return;
    const float* W = (t < 32768) ? W1 : W2;
    unsigned char* oh = (t < 32768) ? o1h : o2h;
    unsigned char* ol = (t < 32768) ? o1l : o2l;
    int u  = t & 32767;
    int r  = u >> 12;
    int j  = (u >> 5) & 127;
    int k  = (u & 31) * 4;
    const float* Wr = W + r * 16384;
    float4 v = make_float4(Wr[(k + 0) * 128 + j], Wr[(k + 1) * 128 + j],
                           Wr[(k + 2) * 128 + j], Wr[(k + 3) * 128 + j]);
    uint2 hi, lo;
    split4(v, hi, lo);
    uint32_t off = (uint32_t)r * 32768u + (uint32_t)j * 256u + (uint32_t)k * 2u;
    *(uint2*)(oh + off) = hi;
    *(uint2*)(ol + off) = lo;
}

// ---------------- mma.sync relation-transform GEMM ---------------------------
static constexpr int S_ELEM = 136;
static constexpr int S_BYTE = S_ELEM * 2;              // 272
static constexpr int TILE_B = 128 * S_BYTE;            // 34816
static constexpr int OFF_A_HI = 0;
static constexpr int OFF_A_LO = TILE_B;                // 34816
static constexpr int OFF_B    = 2 * TILE_B;            // 69632; stage s at +s*2*TILE_B
static constexpr int SMEM_BYTES = OFF_B + 4 * TILE_B;  // 208896

__global__ __launch_bounds__(512, 1)
void rgemm_kernel(const float* __restrict__ A,
                  const uint4* __restrict__ Bh,
                  const uint4* __restrict__ Bl,
                  float* __restrict__ xW) {
    extern __shared__ unsigned char smem[];
    const uint32_t sb = smem_u32(smem);
    const int tid    = threadIdx.x;
    const int wid    = tid >> 5;
    const int lane   = tid & 31;
    const int warp_m = wid & 3;          // 4 tiles of 32 rows
    const int warp_n = wid >> 2;         // 4 tiles of 32 cols
    const int m0     = blockIdx.x * 128;

    // ---- convert A tile (fp32 -> hi/lo bf16) into padded SMEM --------------
    {
        const int cg = tid & 31;         // col group of 4 elems
        const int w  = tid >> 5;         // 0..15
        #pragma unroll
        for (int i = 0; i < 8; i++) {
            int row = w + i * 16;
            int n   = m0 + row;
            float4 v = make_float4(0.f, 0.f, 0.f, 0.f);
            if (n < N_NODES) v = ((const float4*)A)[(size_t)n * 32 + cg];
            uint2 hi, lo;
            split4(v, hi, lo);
            uint32_t off = (uint32_t)row * S_BYTE + (uint32_t)cg * 8;
            *(uint2*)(smem + OFF_A_HI + off) = hi;
            *(uint2*)(smem + OFF_A_LO + off) = lo;
        }
    }

    // ---- ldmatrix fragment addresses (fixed per thread) --------------------
    const int lr = lane & 15;
    const int lc = lane >> 4;
    uint32_t aRow[2], bRow[2];
    #pragma unroll
    for (int mt = 0; mt < 2; mt++)
        aRow[mt] = (uint32_t)(warp_m * 32 + mt * 16 + lr) * S_BYTE + lc * 16;
    #pragma unroll
    for (int g = 0; g < 2; g++)
        bRow[g] = (uint32_t)(warp_n * 32 + g * 16 + lr) * S_BYTE + lc * 16;

    // ---- B double-buffer loader (cp.async, 512 threads) --------------------
    auto load_B = [&](int r, int s) {
        uint32_t dstH = sb + OFF_B + s * (2 * TILE_B);
        uint32_t dstL = dstH + TILE_B;
        const char* srcH = (const char*)Bh + (size_t)r * 32768;
        const char* srcL = (const char*)Bl + (size_t)r * 32768;
        #pragma unroll
        for (int q = 0; q < 4; q++) {
            int i   = tid + q * 512;       // 0..2047 chunks of 16B
            int j   = i >> 4;
            int k16 = i & 15;
            uint32_t doff = (uint32_t)j * S_BYTE + k16 * 16;
            uint32_t soff = (uint32_t)j * 256 + k16 * 16;
            CP_ASYNC16(dstH + doff, srcH + soff);
            CP_ASYNC16(dstL + doff, srcL + soff);
        }
        CP_COMMIT();
    };

    load_B(0, 0);
    __syncthreads();   // A tile visible to all warps

    for (int r = 0; r < N_REL; r++) {
        const int s = r & 1;
        if (r < N_REL - 1) load_B(r + 1, s ^ 1);
        if (r < N_REL - 1) asm volatile("cp.async.wait_group 1;" ::: "memory");
        else               asm volatile("cp.async.wait_group 0;" ::: "memory");
        __syncthreads();

        float c[2][4][4];
        #pragma unroll
        for (int mt = 0; mt < 2; mt++)
            #pragma unroll
            for (int nt = 0; nt < 4; nt++)
                #pragma unroll
                for (int e = 0; e < 4; e++) c[mt][nt][e] = 0.0f;

        const uint32_t bStageH = sb + OFF_B + s * (2 * TILE_B);
        const uint32_t bStageL = bStageH + TILE_B;
        const uint32_t aBaseH  = sb + OFF_A_HI;
        const uint32_t aBaseL  = sb + OFF_A_LO;

        uint32_t ah[2][2][4], al[2][2][4], bh[2][2][4], bl[2][2][4];

        #define LOAD_FRAG(buf, kb)                                                   \
            do {                                                                     \
                _Pragma("unroll")                                                    \
                for (int mt = 0; mt < 2; mt++) {                                     \
                    LDSM_X4(ah[buf][mt][0], ah[buf][mt][1], ah[buf][mt][2],          \
                            ah[buf][mt][3], aBaseH + aRow[mt] + (kb));               \
                    LDSM_X4(al[buf][mt][0], al[buf][mt][1], al[buf][mt][2],          \
                            al[buf][mt][3], aBaseL + aRow[mt] + (kb));               \
                }                                                                    \
                _Pragma("unroll")                                                    \
                for (int g = 0; g < 2; g++) {                                        \
                    LDSM_X4(bh[buf][g][0], bh[buf][g][1], bh[buf][g][2],             \
                            bh[buf][g][3], bStageH + bRow[g] + (kb));                \
                    LDSM_X4(bl[buf][g][0], bl[buf][g][1], bl[buf][g][2],             \
                            bl[buf][g][3], bStageL + bRow[g] + (kb));                \
                }                                                                    \
            } while (0)

        LOAD_FRAG(0, 0);
        #pragma unroll
        for (int ks = 0; ks < 8; ks++) {
            const int cur = ks & 1;
            if (ks < 7) LOAD_FRAG(cur ^ 1, (ks + 1) * 32);
            // c += Ah@Bh + Ah@Bl + Al@Bh (Al@Bl dropped, ~2^-18 relative)
            #pragma unroll
            for (int mt = 0; mt < 2; mt++)
                #pragma unroll
                for (int g = 0; g < 2; g++) {
                    MMA16816(c[mt][g * 2 + 0], ah[cur][mt][0], ah[cur][mt][1],
                             ah[cur][mt][2], ah[cur][mt][3], bh[cur][g][0], bh[cur][g][2]);
                    MMA16816(c[mt][g * 2 + 1], ah[cur][mt][0], ah[cur][mt][1],
                             ah[cur][mt][2], ah[cur][mt][3], bh[cur][g][1], bh[cur][g][3]);
                    MMA16816(c[mt][g * 2 + 0], ah[cur][mt][0], ah[cur][mt][1],
                             ah[cur][mt][2], ah[cur][mt][3], bl[cur][g][0], bl[cur][g][2]);
                    MMA16816(c[mt][g * 2 + 1], ah[cur][mt][0], ah[cur][mt][1],
                             ah[cur][mt][2], ah[cur][mt][3], bl[cur][g][1], bl[cur][g][3]);
                    MMA16816(c[mt][g * 2 + 0], al[cur][mt][0], al[cur][mt][1],
                             al[cur][mt][2], al[cur][mt][3], bh[cur][g][0], bh[cur][g][2]);
                    MMA16816(c[mt][g * 2 + 1], al[cur][mt][0], al[cur][mt][1],
                             al[cur][mt][2], al[cur][mt][3], bh[cur][g][1], bh[cur][g][3]);
                }
        }
        #undef LOAD_FRAG

        // ---- epilogue: direct stores to xW[n][r][d] ------------------------
        const int gid = lane >> 2;
        const int tig = lane & 3;
        #pragma unroll
        for (int mt = 0; mt < 2; mt++) {
            int rowA = warp_m * 32 + mt * 16 + gid;
            int nA = m0 + rowA;
            int nB = nA + 8;
            float* baseA = (nA < N_NODES) ? &xW[((size_t)nA * N_REL + r) * DIM] : nullptr;
            float* baseB = (nB < N_NODES) ? &xW[((size_t)nB * N_REL + r) * DIM] : nullptr;
            #pragma unroll
            for (int nt = 0; nt < 4; nt++) {
                int d = warp_n * 32 + nt * 8 + 2 * tig;
                if (baseA) *(float2*)&baseA[d] = make_float2(c[mt][nt][0], c[mt][nt][1]);
                if (baseB) *(float2*)&baseB[d] = make_float2(c[mt][nt][2], c[mt][nt][3]);
            }
        }
        __syncthreads();   // stage s free for next prefetch overwrite
    }
}

// ---------------- CSR gather aggregation --------------------------------------
// One warp per destination node; lane covers 4 dims (float4).
// MODE 0: z1 = relu(sum + b1)          -> g_z1
// MODE 1: z2 = sum + b2; out = combine -> out (both halves)
template <int MODE>
__global__ __launch_bounds__(256)
void agg_kernel(const float* __restrict__ bias,
                const float* __restrict__ x,
                float* __restrict__ out) {
    const int wid  = (blockIdx.x * 256 + threadIdx.x) >> 5;
    const int lane = threadIdx.x & 31;
    if (wid >= N_NODES) return;
    const int n = wid;
    int e   = g_rowptr[n];
    int end = g_rowptr[n + 1];

    float4 acc = make_float4(0.f, 0.f, 0.f, 0.f);
    for (; e + 1 < end; e += 2) {
        int2 r0 = g_erec[e];
        int2 r1 = g_erec[e + 1];
        float4 v0 = ((const float4*)&g_xW[(size_t)r0.x * DIM])[lane];
        float4 v1 = ((const float4*)&g_xW[(size_t)r1.x * DIM])[lane];
        float c0 = __int_as_float(r0.y);
        float c1 = __int_as_float(r1.y);
        acc.x += c0 * v0.x + c1 * v1.x;
        acc.y += c0 * v0.y + c1 * v1.y;
        acc.z += c0 * v0.z + c1 * v1.z;
        acc.w += c0 * v0.w + c1 * v1.w;
    }
    if (e < end) {
        int2 r0 = g_erec[e];
        float4 v0 = ((const float4*)&g_xW[(size_t)r0.x * DIM])[lane];
        float c0 = __int_as_float(r0.y);
        acc.x += c0 * v0.x;
        acc.y += c0 * v0.y;
        acc.z += c0 * v0.z;
        acc.w += c0 * v0.w;
    }

    float4 b = ((const float4*)bias)[lane];
    if (MODE == 0) {
        float4 o;
        o.x = fmaxf(acc.x + b.x, 0.f);
        o.y = fmaxf(acc.y + b.y, 0.f);
        o.z = fmaxf(acc.z + b.z, 0.f);
        o.w = fmaxf(acc.w + b.w, 0.f);
        ((float4*)g_z1)[(size_t)n * 32 + lane] = o;
    } else {
        float4 z2 = make_float4(acc.x + b.x, acc.y + b.y, acc.z + b.z, acc.w + b.w);
        float4 z1 = ((const float4*)g_z1)[(size_t)n * 32 + lane];
        float4 xv = ((const float4*)x)[(size_t)n * 32 + lane];
        float4 st, sh;
        st.x = (xv.x + z1.x + z2.x) * 0.25f;  sh.x = (z1.x + z2.x) * (1.f / 3.f);
        st.y = (xv.y + z1.y + z2.y) * 0.25f;  sh.y = (z1.y + z2.y) * (1.f / 3.f);
        st.z = (xv.z + z1.z + z2.z) * 0.25f;  sh.z = (z1.z + z2.z) * (1.f / 3.f);
        st.w = (xv.w + z1.w + z2.w) * 0.25f;  sh.w = (z1.w + z2.w) * (1.f / 3.f);
        ((float4*)out)[(size_t)n * 32 + lane] = st;
        ((float4*)out)[(size_t)(N_NODES + n) * 32 + lane] = sh;
    }
}

// ---------------- launch -----------------------------------------------------
extern "C" void kernel_launch(void* const* d_in, const int* in_sizes, int n_in,
                              void* d_out, int out_size) {
    const float* x  = (const float*)d_in[0];
    const int*   ei = (const int*)  d_in[1];
    const int*   et = (const int*)  d_in[2];
    const float* ew = (const float*)d_in[3];
    const float* W1 = (const float*)d_in[4];
    const float* b1 = (const float*)d_in[5];
    const float* W2 = (const float*)d_in[6];
    const float* b2 = (const float*)d_in[7];
    float* out = (float*)d_out;

    const int* row = ei;
    const int* col = ei + N_EDGES;

    void *p_z1, *p_xW, *p_B1h, *p_B1l, *p_B2h, *p_B2l;
    cudaGetSymbolAddress(&p_z1,  g_z1);
    cudaGetSymbolAddress(&p_xW,  g_xW);
    cudaGetSymbolAddress(&p_B1h, g_B1h);
    cudaGetSymbolAddress(&p_B1l, g_B1l);
    cudaGetSymbolAddress(&p_B2h, g_B2h);
    cudaGetSymbolAddress(&p_B2l, g_B2l);

    cudaFuncSetAttribute(rgemm_kernel, cudaFuncAttributeMaxDynamicSharedMemorySize, SMEM_BYTES);

    const int EB = (N_EDGES + 255) / 256;
    const int NB = (N_NODES + 255) / 256;
    const int GB = (N_NODES + 127) / 128;           // 782
    const int AB = (N_NODES * 32 + 255) / 256;      // 12500 (warp per node)

    // CSR build first (scan is a tiny serial kernel; keep it off the critical
    // path between rgemm and agg)
    zero_cnt_kernel<<<NB, 256>>>();                                        // [0]
    hist_kernel<<<EB, 256>>>(col);                                         // [1]
    scan_kernel<<<1, 1024>>>();                                            // [2]
    fill_kernel<<<EB, 256>>>(row, col, et, ew);                            // [3]
    prepack_kernel<<<256, 256>>>(W1, W2,
                                 (unsigned char*)p_B1h, (unsigned char*)p_B1l,
                                 (unsigned char*)p_B2h, (unsigned char*)p_B2l); // [4]

    // conv 1: transform + aggregate(+bias+relu)
    rgemm_kernel<<<GB, 512, SMEM_BYTES>>>(x, (const uint4*)p_B1h,
                                          (const uint4*)p_B1l, (float*)p_xW);   // [5]
    agg_kernel<0><<<AB, 256>>>(b1, x, out);                                // [6]

    // conv 2: transform + aggregate(+bias+final combine)
    rgemm_kernel<<<GB, 512, SMEM_BYTES>>>((const float*)p_z1, (const uint4*)p_B2h,
                                          (const uint4*)p_B2l, (float*)p_xW);   // [7]
    agg_kernel<1><<<AB, 256>>>(b2, x, out);                                // [8]
}

// round 8
// speedup vs baseline: 1.1677x; 1.1677x over previous
#include <cuda_runtime.h>
#include <cuda_bf16.h>
#include <math.h>
#include <stdint.h>

#define N_NODES 100000
#define DIM     128
#define N_REL   8
#define N_EDGES 640000
#define E_PAD   (N_EDGES + 1024)          // 641024, 128*8 pad headroom
#define MAX_TILES 5008

// ---------------- scratch (static device globals; no allocation) -------------
__device__ float g_deg  [N_NODES];
__device__ float g_dinv [N_NODES];
__device__ int   g_tcnt [N_REL];
__device__ int   g_tcur [N_REL];
__device__ int   g_tb   [N_REL + 1];     // tile base per type (cumulative)
__device__ int   g_erow [E_PAD];
__device__ int   g_ecol [E_PAD];
__device__ float g_ecoef[E_PAD];
__device__ float g_agg  [(size_t)N_NODES * DIM];
__device__ float g_z1   [(size_t)N_NODES * DIM];
// prepacked, transposed (W^T: [r][j=out][k=in]) bf16 hi/lo weight images
__device__ uint4 g_B1h[16384];   // 8 rel * 32768 B each
__device__ uint4 g_B1l[16384];
__device__ uint4 g_B2h[16384];
__device__ uint4 g_B2l[16384];

// ===================== helpers ===============================================
__device__ __forceinline__ uint32_t smem_u32(const void* p) {
    uint32_t a;
    asm("{ .reg .u64 t; cvta.to.shared.u64 t, %1; cvt.u32.u64 %0, t; }" : "=r"(a) : "l"(p));
    return a;
}

__device__ __forceinline__ void split4(float4 v, uint2& hi, uint2& lo) {
    __nv_bfloat16 h0 = __float2bfloat16(v.x), h1 = __float2bfloat16(v.y);
    __nv_bfloat16 h2 = __float2bfloat16(v.z), h3 = __float2bfloat16(v.w);
    __nv_bfloat16 l0 = __float2bfloat16(v.x - __bfloat162float(h0));
    __nv_bfloat16 l1 = __float2bfloat16(v.y - __bfloat162float(h1));
    __nv_bfloat16 l2 = __float2bfloat16(v.z - __bfloat162float(h2));
    __nv_bfloat16 l3 = __float2bfloat16(v.w - __bfloat162float(h3));
    hi.x = (uint32_t)__bfloat16_as_ushort(h0) | ((uint32_t)__bfloat16_as_ushort(h1) << 16);
    hi.y = (uint32_t)__bfloat16_as_ushort(h2) | ((uint32_t)__bfloat16_as_ushort(h3) << 16);
    lo.x = (uint32_t)__bfloat16_as_ushort(l0) | ((uint32_t)__bfloat16_as_ushort(l1) << 16);
    lo.y = (uint32_t)__bfloat16_as_ushort(l2) | ((uint32_t)__bfloat16_as_ushort(l3) << 16);
}

#define LDSM_X4(r0, r1, r2, r3, addr) \
    asm volatile("ldmatrix.sync.aligned.m8n8.x4.shared.b16 {%0,%1,%2,%3}, [%4];" \
                 : "=r"(r0), "=r"(r1), "=r"(r2), "=r"(r3) : "r"(addr))

#define MMA16816(c, a0, a1, a2, a3, b0, b1) \
    asm volatile("mma.sync.aligned.m16n8k16.row.col.f32.bf16.bf16.f32 " \
                 "{%0,%1,%2,%3}, {%4,%5,%6,%7}, {%8,%9}, {%0,%1,%2,%3};" \
                 : "+f"((c)[0]), "+f"((c)[1]), "+f"((c)[2]), "+f"((c)[3]) \
                 : "r"(a0), "r"(a1), "r"(a2), "r"(a3), "r"(b0), "r"(b1))

#define CP_ASYNC16(dst, src) \
    asm volatile("cp.async.ca.shared.global [%0], [%1], 16;" :: "r"(dst), "l"(src) : "memory")
#define CP_COMMIT() asm volatile("cp.async.commit_group;" ::: "memory")

// ---------------- zero everything mutable ------------------------------------
__global__ void zero_all_kernel() {
    int i = blockIdx.x * 256 + threadIdx.x;
    const float4 z4 = make_float4(0.f, 0.f, 0.f, 0.f);
    const int4   zi = make_int4(0, 0, 0, 0);
    if (i < 3200000)                 ((float4*)g_agg)[i] = z4;
    else if (i < 3225000)            ((float4*)g_deg)[i - 3200000] = z4;
    else if (i < 3385256)            ((int4*)g_erow)[i - 3225000] = zi;
    else if (i < 3545512)            ((int4*)g_ecol)[i - 3385256] = zi;
    else if (i < 3705768)            ((float4*)g_ecoef)[i - 3545512] = z4;
    else if (i == 3705768) {
        #pragma unroll
        for (int t = 0; t < N_REL; t++) g_tcnt[t] = 0;
    }
}

// ---------------- degree + type histogram ------------------------------------
__global__ void hist_kernel(const int* __restrict__ col, const int* __restrict__ et) {
    __shared__ int bins[N_REL];
    if (threadIdx.x < N_REL) bins[threadIdx.x] = 0;
    __syncthreads();
    int e = blockIdx.x * 256 + threadIdx.x;
    if (e < N_EDGES) {
        atomicAdd(&g_deg[col[e]], 1.0f);
        atomicAdd(&bins[et[e]], 1);
    }
    __syncthreads();
    if (threadIdx.x < N_REL) atomicAdd(&g_tcnt[threadIdx.x], bins[threadIdx.x]);
}

__global__ void dinv_kernel() {
    int n = blockIdx.x * blockDim.x + threadIdx.x;
    if (n < N_NODES) {
        float d = g_deg[n];
        g_dinv[n] = (d > 0.0f) ? rsqrtf(d) : 0.0f;
    }
}

// tile bases + cursors (1 thread)
__global__ void toff_kernel() {
    int tb = 0;
    for (int t = 0; t < N_REL; t++) {
        g_tb[t] = tb;
        g_tcur[t] = tb * 128;
        tb += (g_tcnt[t] + 127) / 128;
    }
    g_tb[N_REL] = tb;
}

__global__ void fill_kernel(const int* __restrict__ row,
                            const int* __restrict__ col,
                            const int* __restrict__ etype,
                            const float* __restrict__ ew) {
    int e = blockIdx.x * 256 + threadIdx.x;
    if (e >= N_EDGES) return;
    int r = row[e], c = col[e], t = etype[e];
    float cf = g_dinv[r] * g_dinv[c] * ew[e];
    int p = atomicAdd(&g_tcur[t], 1);
    g_erow[p] = r;
    g_ecol[p] = c;
    g_ecoef[p] = cf;
}

// ---------------- weight prepack: transpose + bf16-split (both W) ------------
__global__ void prepack_kernel(const float* __restrict__ W1,
                               const float* __restrict__ W2,
                               unsigned char* __restrict__ o1h,
                               unsigned char* __restrict__ o1l,
                               unsigned char* __restrict__ o2h,
                               unsigned char* __restrict__ o2l) {
    int t = blockIdx.x * 256 + threadIdx.x;     // 65536 threads
    if (t >= 2 * N_REL * 128 * 32) return;
    const float* W = (t < 32768) ? W1 : W2;
    unsigned char* oh = (t < 32768) ? o1h : o2h;
    unsigned char* ol = (t < 32768) ? o1l : o2l;
    int u  = t & 32767;
    int r  = u >> 12;
    int j  = (u >> 5) & 127;
    int k  = (u & 31) * 4;
    const float* Wr = W + r * 16384;
    float4 v = make_float4(Wr[(k + 0) * 128 + j], Wr[(k + 1) * 128 + j],
                           Wr[(k + 2) * 128 + j], Wr[(k + 3) * 128 + j]);
    uint2 hi, lo;
    split4(v, hi, lo);
    uint32_t off = (uint32_t)r * 32768u + (uint32_t)j * 256u + (uint32_t)k * 2u;
    *(uint2*)(oh + off) = hi;
    *(uint2*)(ol + off) = lo;
}

// ---------------- edge-batched GEMM: agg[col] += coef * (x[row] @ W_t) -------
static constexpr int S_ELEM = 136;
static constexpr int S_BYTE = S_ELEM * 2;              // 272
static constexpr int TILE_B = 128 * S_BYTE;            // 34816
static constexpr int OFF_A_HI = 0;
static constexpr int OFF_A_LO = TILE_B;                // 34816
static constexpr int OFF_B_HI = 2 * TILE_B;            // 69632
static constexpr int OFF_B_LO = 3 * TILE_B;            // 104448
static constexpr int OFF_COL  = 4 * TILE_B;            // 139264
static constexpr int OFF_COEF = OFF_COL + 512;         // 139776
static constexpr int OFF_ROW  = OFF_COEF + 512;        // 140288
static constexpr int SMEM_BYTES = OFF_ROW + 512;       // 140800
static constexpr int STAGE_STRIDE = 132;               // floats; 128*132*4=67584 < OFF_B_HI

__global__ __launch_bounds__(512, 1)
void egemm_kernel(const float* __restrict__ A,
                  const uint4* __restrict__ Bh,
                  const uint4* __restrict__ Bl) {
    extern __shared__ unsigned char smem[];
    const uint32_t sb = smem_u32(smem);
    const int tid    = threadIdx.x;
    const int wid    = tid >> 5;
    const int lane   = tid & 31;
    const int warp_m = wid & 3;
    const int warp_n = wid >> 2;
    const int bid    = blockIdx.x;

    if (bid >= g_tb[N_REL]) return;
    int t = 0;
    #pragma unroll
    for (int i = 1; i < N_REL; i++)
        if (bid >= g_tb[i]) t = i;
    const int ebase = bid * 128;

    // B load (cp.async, single stage; W_t prepacked, L2-resident)
    {
        uint32_t dstH = sb + OFF_B_HI, dstL = sb + OFF_B_LO;
        const char* srcH = (const char*)Bh + (size_t)t * 32768;
        const char* srcL = (const char*)Bl + (size_t)t * 32768;
        #pragma unroll
        for (int q = 0; q < 4; q++) {
            int i   = tid + q * 512;
            int j   = i >> 4;
            int k16 = i & 15;
            uint32_t doff = (uint32_t)j * S_BYTE + k16 * 16;
            uint32_t soff = (uint32_t)j * 256 + k16 * 16;
            CP_ASYNC16(dstH + doff, srcH + soff);
            CP_ASYNC16(dstL + doff, srcL + soff);
        }
        CP_COMMIT();
    }

    // edge metadata for this tile
    if (tid < 128) {
        ((int*)  (smem + OFF_ROW ))[tid] = g_erow [ebase + tid];
        ((int*)  (smem + OFF_COL ))[tid] = g_ecol [ebase + tid];
        ((float*)(smem + OFF_COEF))[tid] = g_ecoef[ebase + tid];
    }
    __syncthreads();

    // gather source rows + bf16 hi/lo split into padded SMEM
    {
        const int* rowbuf = (const int*)(smem + OFF_ROW);
        const int cg    = tid & 31;
        const int rbase = tid >> 5;      // 0..15
        #pragma unroll
        for (int i = 0; i < 8; i++) {
            int row  = rbase + i * 16;
            int srow = rowbuf[row];
            float4 v = ((const float4*)A)[(size_t)srow * 32 + cg];
            uint2 hi, lo;
            split4(v, hi, lo);
            uint32_t off = (uint32_t)row * S_BYTE + (uint32_t)cg * 8;
            *(uint2*)(smem + OFF_A_HI + off) = hi;
            *(uint2*)(smem + OFF_A_LO + off) = lo;
        }
    }
    asm volatile("cp.async.wait_group 0;" ::: "memory");
    __syncthreads();

    // ldmatrix fragment addresses
    const int lr = lane & 15;
    const int lc = lane >> 4;
    uint32_t aRow[2], bRow[2];
    #pragma unroll
    for (int mt = 0; mt < 2; mt++)
        aRow[mt] = (uint32_t)(warp_m * 32 + mt * 16 + lr) * S_BYTE + lc * 16;
    #pragma unroll
    for (int g = 0; g < 2; g++)
        bRow[g] = (uint32_t)(warp_n * 32 + g * 16 + lr) * S_BYTE + lc * 16;

    float c[2][4][4];
    #pragma unroll
    for (int mt = 0; mt < 2; mt++)
        #pragma unroll
        for (int nt = 0; nt < 4; nt++)
            #pragma unroll
            for (int e = 0; e < 4; e++) c[mt][nt][e] = 0.0f;

    const uint32_t bStageH = sb + OFF_B_HI;
    const uint32_t bStageL = sb + OFF_B_LO;
    const uint32_t aBaseH  = sb + OFF_A_HI;
    const uint32_t aBaseL  = sb + OFF_A_LO;

    uint32_t ah[2][2][4], al[2][2][4], bh[2][2][4], bl[2][2][4];

    #define LOAD_FRAG(buf, kb)                                                   \
        do {                                                                     \
            _Pragma("unroll")                                                    \
            for (int mt = 0; mt < 2; mt++) {                                     \
                LDSM_X4(ah[buf][mt][0], ah[buf][mt][1], ah[buf][mt][2],          \
                        ah[buf][mt][3], aBaseH + aRow[mt] + (kb));               \
                LDSM_X4(al[buf][mt][0], al[buf][mt][1], al[buf][mt][2],          \
                        al[buf][mt][3], aBaseL + aRow[mt] + (kb));               \
            }                                                                    \
            _Pragma("unroll")                                                    \
            for (int g = 0; g < 2; g++) {                                        \
                LDSM_X4(bh[buf][g][0], bh[buf][g][1], bh[buf][g][2],             \
                        bh[buf][g][3], bStageH + bRow[g] + (kb));                \
                LDSM_X4(bl[buf][g][0], bl[buf][g][1], bl[buf][g][2],             \
                        bl[buf][g][3], bStageL + bRow[g] + (kb));                \
            }                                                                    \
        } while (0)

    LOAD_FRAG(0, 0);
    #pragma unroll
    for (int ks = 0; ks < 8; ks++) {
        const int cur = ks & 1;
        if (ks < 7) LOAD_FRAG(cur ^ 1, (ks + 1) * 32);
        // c += Ah@Bh + Ah@Bl + Al@Bh (Al@Bl dropped, ~2^-18 relative)
        #pragma unroll
        for (int mt = 0; mt < 2; mt++)
            #pragma unroll
            for (int g = 0; g < 2; g++) {
                MMA16816(c[mt][g * 2 + 0], ah[cur][mt][0], ah[cur][mt][1],
                         ah[cur][mt][2], ah[cur][mt][3], bh[cur][g][0], bh[cur][g][2]);
                MMA16816(c[mt][g * 2 + 1], ah[cur][mt][0], ah[cur][mt][1],
                         ah[cur][mt][2], ah[cur][mt][3], bh[cur][g][1], bh[cur][g][3]);
                MMA16816(c[mt][g * 2 + 0], ah[cur][mt][0], ah[cur][mt][1],
                         ah[cur][mt][2], ah[cur][mt][3], bl[cur][g][0], bl[cur][g][2]);
                MMA16816(c[mt][g * 2 + 1], ah[cur][mt][0], ah[cur][mt][1],
                         ah[cur][mt][2], ah[cur][mt][3], bl[cur][g][1], bl[cur][g][3]);
                MMA16816(c[mt][g * 2 + 0], al[cur][mt][0], al[cur][mt][1],
                         al[cur][mt][2], al[cur][mt][3], bh[cur][g][0], bh[cur][g][2]);
                MMA16816(c[mt][g * 2 + 1], al[cur][mt][0], al[cur][mt][1],
                         al[cur][mt][2], al[cur][mt][3], bh[cur][g][1], bh[cur][g][3]);
            }
    }
    #undef LOAD_FRAG

    __syncthreads();   // all A/B SMEM reads done; safe to overwrite with stage

    // stage message tile to SMEM (row-major, padded stride)
    float* stage = (float*)smem;
    const int gid = lane >> 2;
    const int tig = lane & 3;
    #pragma unroll
    for (int mt = 0; mt < 2; mt++) {
        int rA = warp_m * 32 + mt * 16 + gid;
        int rB = rA + 8;
        #pragma unroll
        for (int nt = 0; nt < 4; nt++) {
            int d = warp_n * 32 + nt * 8 + 2 * tig;
            stage[rA * STAGE_STRIDE + d]     = c[mt][nt][0];
            stage[rA * STAGE_STRIDE + d + 1] = c[mt][nt][1];
            stage[rB * STAGE_STRIDE + d]     = c[mt][nt][2];
            stage[rB * STAGE_STRIDE + d + 1] = c[mt][nt][3];
        }
    }
    __syncthreads();

    // coalesced vector-RED into agg[col] (L2-resident, 51 MB footprint)
    const float* coefbuf = (const float*)(smem + OFF_COEF);
    const int*   colbuf  = (const int*)  (smem + OFF_COL);
    #pragma unroll
    for (int i = 0; i < 8; i++) {
        int row  = wid * 8 + i;
        float cf = coefbuf[row];
        if (cf != 0.0f) {
            int cn = colbuf[row];
            float4 v = *(const float4*)&stage[row * STAGE_STRIDE + lane * 4];
            float* dst = &g_agg[(size_t)cn * DIM + lane * 4];
            asm volatile("red.global.add.v4.f32 [%0], {%1, %2, %3, %4};"
                         :: "l"(dst), "f"(cf * v.x), "f"(cf * v.y),
                            "f"(cf * v.z), "f"(cf * v.w)
                         : "memory");
        }
    }
}

// ---------------- bias + relu -> z1, re-zero agg for conv2 --------------------
__global__ void bias_relu_zero_kernel(const float* __restrict__ b1) {
    int i = blockIdx.x * blockDim.x + threadIdx.x;       // float4 index
    if (i < N_NODES * DIM / 4) {
        float4 a = ((const float4*)g_agg)[i];
        const float4 b = ((const float4*)b1)[i & 31];
        float4 o;
        o.x = fmaxf(a.x + b.x, 0.f);
        o.y = fmaxf(a.y + b.y, 0.f);
        o.z = fmaxf(a.z + b.z, 0.f);
        o.w = fmaxf(a.w + b.w, 0.f);
        ((float4*)g_z1)[i] = o;
        ((float4*)g_agg)[i] = make_float4(0.f, 0.f, 0.f, 0.f);
    }
}

// ---------------- final combine ----------------------------------------------
__global__ void final_kernel(const float* __restrict__ x,
                             const float* __restrict__ b2,
                             float* __restrict__ out) {
    int i = blockIdx.x * blockDim.x + threadIdx.x;       // float4 index
    if (i < N_NODES * DIM / 4) {
        float4 a  = ((const float4*)g_agg)[i];
        float4 b  = ((const float4*)b2)[i & 31];
        float4 z1 = ((const float4*)g_z1)[i];
        float4 xv = ((const float4*)x)[i];
        float4 st, sh;
        st.x = (xv.x + z1.x + a.x + b.x) * 0.25f;  sh.x = (z1.x + a.x + b.x) * (1.f / 3.f);
        st.y = (xv.y + z1.y + a.y + b.y) * 0.25f;  sh.y = (z1.y + a.y + b.y) * (1.f / 3.f);
        st.z = (xv.z + z1.z + a.z + b.z) * 0.25f;  sh.z = (z1.z + a.z + b.z) * (1.f / 3.f);
        st.w = (xv.w + z1.w + a.w + b.w) * 0.25f;  sh.w = (z1.w + a.w + b.w) * (1.f / 3.f);
        ((float4*)out)[i] = st;
        ((float4*)out)[(size_t)N_NODES * DIM / 4 + i] = sh;
    }
}

// ---------------- launch -----------------------------------------------------
extern "C" void kernel_launch(void* const* d_in, const int* in_sizes, int n_in,
                              void* d_out, int out_size) {
    const float* x  = (const float*)d_in[0];
    const int*   ei = (const int*)  d_in[1];
    const int*   et = (const int*)  d_in[2];
    const float* ew = (const float*)d_in[3];
    const float* W1 = (const float*)d_in[4];
    const float* b1 = (const float*)d_in[5];
    const float* W2 = (const float*)d_in[6];
    const float* b2 = (const float*)d_in[7];
    float* out = (float*)d_out;

    const int* row = ei;
    const int* col = ei + N_EDGES;

    void *p_z1, *p_B1h, *p_B1l, *p_B2h, *p_B2l;
    cudaGetSymbolAddress(&p_z1,  g_z1);
    cudaGetSymbolAddress(&p_B1h, g_B1h);
    cudaGetSymbolAddress(&p_B1l, g_B1l);
    cudaGetSymbolAddress(&p_B2h, g_B2h);
    cudaGetSymbolAddress(&p_B2l, g_B2l);

    cudaFuncSetAttribute(egemm_kernel, cudaFuncAttributeMaxDynamicSharedMemorySize, SMEM_BYTES);

    const int EB = (N_EDGES + 255) / 256;
    const int NB = (N_NODES + 255) / 256;
    const int V4 = (N_NODES * DIM / 4 + 255) / 256;
    const int ZB = (3705769 + 255) / 256;

    zero_all_kernel<<<ZB, 256>>>();                                        // [0]
    hist_kernel<<<EB, 256>>>(col, et);                                     // [1]
    dinv_kernel<<<NB, 256>>>();                                            // [2]
    toff_kernel<<<1, 1>>>();                                               // [3]
    fill_kernel<<<EB, 256>>>(row, col, et, ew);                            // [4]
    prepack_kernel<<<256, 256>>>(W1, W2,
                                 (unsigned char*)p_B1h, (unsigned char*)p_B1l,
                                 (unsigned char*)p_B2h, (unsigned char*)p_B2l); // [5]

    // conv 1: agg += coef * (x[row] @ W1[t]) scattered to col
    egemm_kernel<<<MAX_TILES, 512, SMEM_BYTES>>>(x, (const uint4*)p_B1h,
                                                 (const uint4*)p_B1l);     // [6]
    bias_relu_zero_kernel<<<V4, 256>>>(b1);                                // [7]

    // conv 2: agg += coef * (z1[row] @ W2[t]) scattered to col
    egemm_kernel<<<MAX_TILES, 512, SMEM_BYTES>>>((const float*)p_z1,
                                                 (const uint4*)p_B2h,
                                                 (const uint4*)p_B2l);     // [8]
    final_kernel<<<V4, 256>>>(x, b2, out);                                 // [9]
}